// round 5
// baseline (speedup 1.0000x reference)
#include <cuda_runtime.h>
#include <cstdint>

#define N_NODES 50000
#define N_EDGES 800000
#define HID 128

// ---------------- scratch ----------------
__device__ float    g_h  [N_NODES*HID];        // h buffer A (inproj out; final after L3)
__device__ float    g_hB [N_NODES*HID];        // h buffer B (ping-pong)
__device__ float    g_An [N_NODES*HID];
__device__ float    g_Bn [N_NODES*HID];
__device__ int      g_cntfill[2*N_NODES];      // [cnt | fill]
__device__ int      g_rowptr[N_NODES+1];
__device__ int      g_csr[N_EDGES];
__device__ uint32_t g_Wt [4*HID*256];          // tf32 [l][n][k] combined Wl|Wr
__device__ uint32_t g_W1s[2*HID*HID];          // tf32 [slice][n][k] from W1
__device__ uint32_t g_W2u[HID*64];             // tf32 [k][c] W2 transposed
__device__ float    g_W1c[8*HID];              // fp32 W1 cols 256..263 transposed

// ---------------- tf32 mma helpers ----------------
__device__ __forceinline__ uint32_t f2tf(float f){
    uint32_t r;
    asm("cvt.rna.tf32.f32 %0, %1;" : "=r"(r) : "f"(f));
    return r;
}
__device__ __forceinline__ void mma_tf32(float* c, const uint32_t* a, uint32_t b0, uint32_t b1){
    asm volatile("mma.sync.aligned.m16n8k8.row.col.f32.tf32.tf32.f32 "
        "{%0,%1,%2,%3}, {%4,%5,%6,%7}, {%8,%9}, {%0,%1,%2,%3};"
        : "+f"(c[0]), "+f"(c[1]), "+f"(c[2]), "+f"(c[3])
        : "r"(a[0]), "r"(a[1]), "r"(a[2]), "r"(a[3]), "r"(b0), "r"(b1));
}

// ---------------- combo: hist (edge blocks) + input projection (node blocks) ----------------
#define EB ((N_EDGES+255)/256)          // 3125
#define NB ((N_NODES+1)/2)              // 25000

__global__ void hist_inproj_k(const int* __restrict__ dst, const float* __restrict__ x,
                              const float* __restrict__ Win, const float* __restrict__ bin){
    if(blockIdx.x < EB){
        int i = blockIdx.x*256 + threadIdx.x;
        if(i < N_EDGES) atomicAdd(&g_cntfill[dst[i]], 1);
        return;
    }
    __shared__ float xs[2][16];
    int tid = threadIdx.x;
    int n0 = (blockIdx.x - EB)*2;
    if(tid < 32){
        int nn = tid/16, k = tid%16;
        int n = n0 + nn;
        xs[nn][k] = (n < N_NODES) ? x[n*16 + k] : 0.f;
    }
    __syncthreads();
    int nn = tid/HID, c = tid%HID;
    int n = n0 + nn;
    if(n < N_NODES){
        float acc = bin[c];
        const float* w = Win + c*16;
        #pragma unroll
        for(int k = 0; k < 16; k++) acc += xs[nn][k]*w[k];
        g_h[n*HID + c] = acc;
    }
}

__global__ void scan_k(){
    __shared__ int s[1024];
    int tid = threadIdx.x;
    int run = 0;
    for(int base = 0; base < N_NODES; base += 1024){
        int i = base + tid;
        int v = (i < N_NODES) ? g_cntfill[i] : 0;
        s[tid] = v;
        __syncthreads();
        for(int off = 1; off < 1024; off <<= 1){
            int t = (tid >= off) ? s[tid-off] : 0;
            __syncthreads();
            s[tid] += t;
            __syncthreads();
        }
        if(i < N_NODES) g_rowptr[i] = run + s[tid] - v;
        run += s[1023];
        __syncthreads();
    }
    if(tid == 0) g_rowptr[N_NODES] = run;
}

__global__ void fill_k(const int* __restrict__ src, const int* __restrict__ dst){
    int i = blockIdx.x*blockDim.x + threadIdx.x;
    if(i < N_EDGES){
        int d = dst[i];
        int pos = g_rowptr[d] + atomicAdd(&g_cntfill[N_NODES + d], 1);
        g_csr[pos] = src[i];
    }
}

// ---------------- weight prep: tf32 pre-conversion ----------------
__global__ void prep_w(const float* __restrict__ W1, const float* __restrict__ W2,
                       const float* __restrict__ Wl, const float* __restrict__ Wr){
    int i = blockIdx.x*blockDim.x + threadIdx.x;
    if(i < 4*HID*256){
        int l = i >> 15; int r = i & 32767; int n = r >> 8, k = r & 255;
        float v = (k < 128) ? Wl[l*16384 + n*128 + k] : Wr[l*16384 + n*128 + (k-128)];
        g_Wt[i] = f2tf(v);
    }
    if(i < 2*HID*HID){
        int s = i >> 14; int r = i & 16383; int n = r >> 7, k = r & 127;
        g_W1s[i] = f2tf(W1[n*264 + s*128 + k]);
    }
    if(i < HID*64){ int k = i/64, c = i%64; g_W2u[i] = f2tf(W2[c*HID + k]); }
    if(i < 8*HID) { int k = i/HID, c = i%HID; g_W1c[i] = W1[c*264 + 256 + k]; }
}

// ---------------- fused layer: agg (CSR gather-mean) + tf32 GEMM K=256 + bias+LN+ReLU ----------------
// dyn smem: Aagg[128*132]u32 | As[128*36]u32 | Bs[128*36]u32 | prm[384]f | ps[256]f | pq[256]f
#define FG_AAGG 0
#define FG_AS   (128*132)
#define FG_BS   (FG_AS + 128*36)
#define FG_PRM  (FG_BS + 128*36)
#define FG_PS   (FG_PRM + 384)
#define FG_PQ   (FG_PS + 256)
#define FG_SMEM ((FG_PQ + 256)*4)

__global__ void __launch_bounds__(256) layer_f(
        const float* __restrict__ hin, float* __restrict__ hout,
        const uint32_t* __restrict__ Wt,
        const float* __restrict__ bias, const float* __restrict__ lng,
        const float* __restrict__ lnb){
    extern __shared__ uint32_t smu[];
    uint32_t* Aagg = smu + FG_AAGG;
    uint32_t* As   = smu + FG_AS;
    uint32_t* Bs   = smu + FG_BS;
    float* prm = (float*)(smu + FG_PRM);
    float* ps  = (float*)(smu + FG_PS);
    float* pq  = (float*)(smu + FG_PQ);

    int tid = threadIdx.x;
    int lane = tid & 31, wid = tid >> 5;
    int g = lane >> 2, t = lane & 3;
    int wy = wid & 3, wx = wid >> 2;
    int m0 = blockIdx.x*128;

    if(tid < 128){
        prm[tid] = bias[tid]; prm[128+tid] = lng[tid]; prm[256+tid] = lnb[tid];
    }

    // ---- phase A: aggregate 16 rows per warp into Aagg (tf32) ----
    const float4* hp = reinterpret_cast<const float4*>(hin);
    for(int rr = 0; rr < 16; rr++){
        int r = wid*16 + rr;
        int n = m0 + r;
        float4 acc = make_float4(0.f,0.f,0.f,0.f);
        if(n < N_NODES){
            int beg = g_rowptr[n], end = g_rowptr[n+1];
            int j = beg;
            for(; j + 4 <= end; j += 4){
                int s0 = g_csr[j], s1 = g_csr[j+1], s2 = g_csr[j+2], s3 = g_csr[j+3];
                float4 v0 = hp[s0*32 + lane];
                float4 v1 = hp[s1*32 + lane];
                float4 v2 = hp[s2*32 + lane];
                float4 v3 = hp[s3*32 + lane];
                acc.x += (v0.x+v1.x) + (v2.x+v3.x);
                acc.y += (v0.y+v1.y) + (v2.y+v3.y);
                acc.z += (v0.z+v1.z) + (v2.z+v3.z);
                acc.w += (v0.w+v1.w) + (v2.w+v3.w);
            }
            for(; j < end; j++){
                int s = g_csr[j];
                float4 v = hp[s*32 + lane];
                acc.x += v.x; acc.y += v.y; acc.z += v.z; acc.w += v.w;
            }
            float inv = (end > beg) ? 1.0f/(float)(end - beg) : 0.0f;
            acc.x *= inv; acc.y *= inv; acc.z *= inv; acc.w *= inv;
        }
        uint32_t* d = Aagg + r*132 + lane*4;
        d[0] = f2tf(acc.x); d[1] = f2tf(acc.y); d[2] = f2tf(acc.z); d[3] = f2tf(acc.w);
    }
    __syncthreads();

    float c[2][8][4];
    #pragma unroll
    for(int mi = 0; mi < 2; mi++)
        #pragma unroll
        for(int nf = 0; nf < 8; nf++)
            #pragma unroll
            for(int j = 0; j < 4; j++) c[mi][nf][j] = 0.f;

    // ---- main loop: 8 chunks of K=32 ----
    for(int ch = 0; ch < 8; ch++){
        {
            #pragma unroll
            for(int i = 0; i < 4; i++){
                int s = tid + i*256;
                int r = s >> 3, c4 = (s & 7)*4;
                uint4 bv = *(const uint4*)(Wt + r*256 + ch*32 + c4);
                *(uint4*)(Bs + r*36 + c4) = bv;
            }
            if(ch >= 4){
                int kc = (ch - 4)*32;
                #pragma unroll
                for(int i = 0; i < 4; i++){
                    int s = tid + i*256;
                    int r = s >> 3, c4 = (s & 7)*4;
                    int mr = m0 + r; if(mr >= N_NODES) mr = N_NODES-1;
                    float4 v = *(const float4*)(hin + mr*128 + kc + c4);
                    uint32_t* d = As + r*36 + c4;
                    d[0] = f2tf(v.x); d[1] = f2tf(v.y); d[2] = f2tf(v.z); d[3] = f2tf(v.w);
                }
            }
        }
        __syncthreads();
        const uint32_t* a_sm;
        int astr;
        if(ch < 4){ a_sm = Aagg + (wy*32 + g)*132 + ch*32 + t; astr = 132; }
        else      { a_sm = As   + (wy*32 + g)*36  + t;         astr = 36;  }
        const uint32_t* b_sm = Bs + (wx*64 + g)*36 + t;
        #pragma unroll
        for(int kk = 0; kk < 4; kk++){
            int k0 = kk*8;
            uint32_t a[2][4];
            #pragma unroll
            for(int mi = 0; mi < 2; mi++){
                const uint32_t* p = a_sm + mi*16*astr + k0;
                a[mi][0] = p[0]; a[mi][1] = p[8*astr]; a[mi][2] = p[4]; a[mi][3] = p[8*astr+4];
            }
            #pragma unroll
            for(int nf = 0; nf < 8; nf++){
                const uint32_t* q = b_sm + nf*8*36 + k0;
                uint32_t b0 = q[0], b1 = q[4];
                mma_tf32(c[0][nf], a[0], b0, b1);
                mma_tf32(c[1][nf], a[1], b0, b1);
            }
        }
        __syncthreads();
    }

    // ---- epilogue: bias + LN + ReLU -> hout ----
    int colb = wx*64;
    #pragma unroll
    for(int mi = 0; mi < 2; mi++)
        #pragma unroll
        for(int rr = 0; rr < 2; rr++){
            float s = 0.f, sq = 0.f;
            #pragma unroll
            for(int nf = 0; nf < 8; nf++)
                #pragma unroll
                for(int j = 0; j < 2; j++){
                    int col = colb + nf*8 + 2*t + j;
                    float v = c[mi][nf][rr*2+j] + prm[col];
                    c[mi][nf][rr*2+j] = v;
                    s += v; sq += v*v;
                }
            s  += __shfl_xor_sync(0xffffffffu, s, 1);
            s  += __shfl_xor_sync(0xffffffffu, s, 2);
            sq += __shfl_xor_sync(0xffffffffu, sq, 1);
            sq += __shfl_xor_sync(0xffffffffu, sq, 2);
            if(t == 0){
                int row = wy*32 + mi*16 + rr*8 + g;
                ps[wx*128 + row] = s;
                pq[wx*128 + row] = sq;
            }
        }
    __syncthreads();
    #pragma unroll
    for(int mi = 0; mi < 2; mi++)
        #pragma unroll
        for(int rr = 0; rr < 2; rr++){
            int row = wy*32 + mi*16 + rr*8 + g;
            int m = m0 + row;
            float st  = ps[row] + ps[128+row];
            float sqt = pq[row] + pq[128+row];
            float mu  = st * (1.0f/128.0f);
            float var = sqt * (1.0f/128.0f) - mu*mu;
            float rs  = rsqrtf(var + 1e-5f);
            if(m < N_NODES){
                #pragma unroll
                for(int nf = 0; nf < 8; nf++){
                    int col = colb + nf*8 + 2*t;
                    float2 o;
                    o.x = fmaxf((c[mi][nf][rr*2+0]-mu)*rs*prm[128+col]   + prm[256+col],   0.f);
                    o.y = fmaxf((c[mi][nf][rr*2+1]-mu)*rs*prm[128+col+1] + prm[256+col+1], 0.f);
                    *(float2*)(hout + m*128 + col) = o;
                }
            }
        }
}

// ---------------- An/Bn GEMM: C = h @ W1slice^T (K=128) ----------------
__global__ void __launch_bounds__(256) gemm_ab(){
    __shared__ uint32_t As[128*36];
    __shared__ uint32_t Bs[128*36];

    int tid = threadIdx.x;
    int lane = tid & 31, wid = tid >> 5;
    int g = lane >> 2, t = lane & 3;
    int wy = wid & 3, wx = wid >> 2;
    int m0 = blockIdx.x*128;
    const uint32_t* W = g_W1s + blockIdx.y*16384;

    float c[2][8][4];
    #pragma unroll
    for(int mi = 0; mi < 2; mi++)
        #pragma unroll
        for(int nf = 0; nf < 8; nf++)
            #pragma unroll
            for(int j = 0; j < 4; j++) c[mi][nf][j] = 0.f;

    for(int ch = 0; ch < 4; ch++){
        #pragma unroll
        for(int i = 0; i < 4; i++){
            int s = tid + i*256;
            int r = s >> 3, c4 = (s & 7)*4;
            int mr = m0 + r; if(mr >= N_NODES) mr = N_NODES-1;
            float4 v = *(const float4*)(g_h + mr*128 + ch*32 + c4);
            uint32_t* d = As + r*36 + c4;
            d[0] = f2tf(v.x); d[1] = f2tf(v.y); d[2] = f2tf(v.z); d[3] = f2tf(v.w);
            uint4 bv = *(const uint4*)(W + r*128 + ch*32 + c4);
            *(uint4*)(Bs + r*36 + c4) = bv;
        }
        __syncthreads();
        const uint32_t* a_sm = As + (wy*32 + g)*36 + t;
        const uint32_t* b_sm = Bs + (wx*64 + g)*36 + t;
        #pragma unroll
        for(int kk = 0; kk < 4; kk++){
            int k0 = kk*8;
            uint32_t a[2][4];
            #pragma unroll
            for(int mi = 0; mi < 2; mi++){
                const uint32_t* p = a_sm + mi*16*36 + k0;
                a[mi][0] = p[0]; a[mi][1] = p[8*36]; a[mi][2] = p[4]; a[mi][3] = p[8*36+4];
            }
            #pragma unroll
            for(int nf = 0; nf < 8; nf++){
                const uint32_t* q = b_sm + nf*8*36 + k0;
                uint32_t b0 = q[0], b1 = q[4];
                mma_tf32(c[0][nf], a[0], b0, b1);
                mma_tf32(c[1][nf], a[1], b0, b1);
            }
        }
        __syncthreads();
    }

    float* out = blockIdx.y ? g_Bn : g_An;
    int colb = wx*64;
    #pragma unroll
    for(int mi = 0; mi < 2; mi++)
        #pragma unroll
        for(int rr = 0; rr < 2; rr++){
            int row = wy*32 + mi*16 + rr*8 + g;
            int m = m0 + row;
            if(m < N_NODES){
                #pragma unroll
                for(int nf = 0; nf < 8; nf++){
                    int col = colb + nf*8 + 2*t;
                    *(float2*)(out + m*128 + col) =
                        make_float2(c[mi][nf][rr*2+0], c[mi][nf][rr*2+1]);
                }
            }
        }
}

// ---------------- fused edge head ----------------
#define EH_H1_STRIDE 132
#define EH_W2_STRIDE 72
#define EH_SMEM_FLOATS (128*EH_H1_STRIDE + 128*EH_W2_STRIDE + 8*128 + 128*8 + 128 + 64 + 64)
#define EH_SMEM_BYTES  (EH_SMEM_FLOATS*4 + 2*128*4)

__global__ void __launch_bounds__(256) edge_k(const int* __restrict__ src,
        const int* __restrict__ dst, const float* __restrict__ ea,
        const float* __restrict__ b1, const float* __restrict__ b2,
        const float* __restrict__ W3, const float* __restrict__ b3,
        float* __restrict__ out){
    extern __shared__ float smf[];
    float* H1  = smf;                          // [128][132] (tf32 bits)
    float* W2s = H1  + 128*EH_H1_STRIDE;       // [128 k][72] (tf32 bits)
    float* W1c = W2s + 128*EH_W2_STRIDE;       // [8][128]
    float* eas = W1c + 8*128;                  // [128][8]
    float* b1s = eas + 128*8;                  // [128]
    float* b2s = b1s + 128;                    // [64]
    float* W3s = b2s + 64;                     // [64]
    int*   srcs = (int*)(W3s + 64);            // [128]
    int*   dsts = srcs + 128;                  // [128]

    int tid = threadIdx.x;
    int e0 = blockIdx.x*128;

    if(tid < 128){ srcs[tid] = src[e0+tid]; dsts[tid] = dst[e0+tid]; b1s[tid] = b1[tid]; }
    else if(tid < 192){ int j = tid-128; b2s[j] = b2[j]; W3s[j] = W3[j]; }
    {
        int m = tid >> 1, k = (tid & 1)*4;
        *reinterpret_cast<float4*>(&eas[m*8 + k]) =
            *reinterpret_cast<const float4*>(&ea[(e0+m)*8 + k]);
    }
    {
        int idx = tid*4;
        *reinterpret_cast<float4*>(&W1c[idx]) =
            *reinterpret_cast<const float4*>(&g_W1c[idx]);
    }
    {   // W2 (pre-tf32): [k][64] -> smem [k][72]
        uint32_t* W2u = (uint32_t*)W2s;
        #pragma unroll
        for(int r = 0; r < 8; r++){
            int idx = r*1024 + tid*4;
            int k = idx >> 6, n = idx & 63;
            uint4 v = *reinterpret_cast<const uint4*>(&g_W2u[idx]);
            *(uint4*)(W2u + k*EH_W2_STRIDE + n) = v;
        }
    }
    __syncthreads();

    // phase 1: H1 = relu(An[src]+Bn[dst]+W1c.ea+b1) -> tf32 smem
    {
        int m = tid >> 1, halfc = tid & 1, n0 = halfc*64;
        int s = srcs[m], dd = dsts[m];
        float e8[8];
        #pragma unroll
        for(int k = 0; k < 8; k++) e8[k] = eas[m*8 + k];
        const float* Ap = g_An + s*HID + n0;
        const float* Bp = g_Bn + dd*HID + n0;
        uint32_t* hrowu = (uint32_t*)&H1[m*EH_H1_STRIDE + n0];
        #pragma unroll
        for(int j4 = 0; j4 < 64; j4 += 4){
            float4 a  = *reinterpret_cast<const float4*>(Ap + j4);
            float4 b  = *reinterpret_cast<const float4*>(Bp + j4);
            float4 bb = *reinterpret_cast<const float4*>(&b1s[n0 + j4]);
            float vx = a.x + b.x + bb.x;
            float vy = a.y + b.y + bb.y;
            float vz = a.z + b.z + bb.z;
            float vw = a.w + b.w + bb.w;
            #pragma unroll
            for(int k = 0; k < 8; k++){
                float4 w = *reinterpret_cast<const float4*>(&W1c[k*HID + n0 + j4]);
                vx += e8[k]*w.x; vy += e8[k]*w.y; vz += e8[k]*w.z; vw += e8[k]*w.w;
            }
            hrowu[j4+0] = f2tf(fmaxf(vx,0.f));
            hrowu[j4+1] = f2tf(fmaxf(vy,0.f));
            hrowu[j4+2] = f2tf(fmaxf(vz,0.f));
            hrowu[j4+3] = f2tf(fmaxf(vw,0.f));
        }
    }
    __syncthreads();

    // phase 2: tf32 mma [128x64] = H1 @ W2t ; relu(+b2).W3 + b3
    int lane = tid & 31, wid = tid >> 5;
    int g = lane >> 2, t = lane & 3;
    const uint32_t* H1u = (const uint32_t*)H1;
    const uint32_t* W2u = (const uint32_t*)W2s;

    float c2[8][4];
    #pragma unroll
    for(int nf = 0; nf < 8; nf++)
        #pragma unroll
        for(int j = 0; j < 4; j++) c2[nf][j] = 0.f;

    const uint32_t* a_sm = H1u + (wid*16 + g)*EH_H1_STRIDE + t;
    const uint32_t* b_sm = W2u + t*EH_W2_STRIDE + g;
    #pragma unroll
    for(int kk = 0; kk < 16; kk++){
        int k0 = kk*8;
        uint32_t a[4];
        const uint32_t* p = a_sm + k0;
        a[0] = p[0]; a[1] = p[8*EH_H1_STRIDE]; a[2] = p[4]; a[3] = p[8*EH_H1_STRIDE+4];
        const uint32_t* q = b_sm + k0*EH_W2_STRIDE;
        #pragma unroll
        for(int nf = 0; nf < 8; nf++){
            uint32_t b0 = q[nf*8];
            uint32_t b1v = q[4*EH_W2_STRIDE + nf*8];
            mma_tf32(c2[nf], a, b0, b1v);
        }
    }

    float bias3 = b3[0];
    #pragma unroll
    for(int rr = 0; rr < 2; rr++){
        float p = 0.f;
        #pragma unroll
        for(int nf = 0; nf < 8; nf++)
            #pragma unroll
            for(int j = 0; j < 2; j++){
                int col = nf*8 + 2*t + j;
                p += fmaxf(c2[nf][rr*2+j] + b2s[col], 0.f) * W3s[col];
            }
        p += __shfl_xor_sync(0xffffffffu, p, 1);
        p += __shfl_xor_sync(0xffffffffu, p, 2);
        if(t == 0) out[e0 + wid*16 + rr*8 + g] = p + bias3;
    }
}

// ---------------- launch ----------------
extern "C" void kernel_launch(void* const* d_in, const int* in_sizes, int n_in,
                              void* d_out, int out_size){
    const float* x   = (const float*)d_in[0];
    const int*   ei  = (const int*)  d_in[1];
    const float* ea  = (const float*)d_in[2];
    const float* Win = (const float*)d_in[3];
    const float* bin = (const float*)d_in[4];
    const float* Wl  = (const float*)d_in[5];
    const float* bl  = (const float*)d_in[6];
    const float* Wr  = (const float*)d_in[7];
    const float* lng = (const float*)d_in[8];
    const float* lnb = (const float*)d_in[9];
    const float* W1  = (const float*)d_in[10];
    const float* b1  = (const float*)d_in[11];
    const float* W2  = (const float*)d_in[12];
    const float* b2  = (const float*)d_in[13];
    const float* W3  = (const float*)d_in[14];
    const float* b3  = (const float*)d_in[15];
    const int* src = ei;
    const int* dst = ei + N_EDGES;

    static bool attr_done = false;
    if(!attr_done){
        cudaFuncSetAttribute(layer_f, cudaFuncAttributeMaxDynamicSharedMemorySize, FG_SMEM);
        cudaFuncSetAttribute(edge_k,  cudaFuncAttributeMaxDynamicSharedMemorySize, EH_SMEM_BYTES);
        attr_done = true;
    }

    void* p;
    cudaGetSymbolAddress(&p, g_cntfill);
    cudaMemsetAsync(p, 0, 2*N_NODES*sizeof(int));                       // launch 0

    hist_inproj_k<<<EB + NB, 256>>>(dst, x, Win, bin);                  // launch 1
    scan_k<<<1, 1024>>>();                                              // launch 2
    fill_k<<<(N_EDGES+255)/256, 256>>>(src, dst);                       // launch 3
    prep_w<<<(4*HID*256+255)/256, 256>>>(W1, W2, Wl, Wr);               // launch 4

    const int gb = (N_NODES + 127)/128;  // 391
    float* hA; cudaGetSymbolAddress((void**)&hA, g_h);
    float* hB; cudaGetSymbolAddress((void**)&hB, g_hB);
    uint32_t* Wt0; cudaGetSymbolAddress((void**)&Wt0, g_Wt);
    for(int l = 0; l < 4; l++){
        const float* hin = (l & 1) ? hB : hA;
        float*       hout = (l & 1) ? hA : hB;
        layer_f<<<gb, 256, FG_SMEM>>>(hin, hout, Wt0 + l*HID*256,       // launch 5 = layer 0 (profiled)
                                      bl + l*HID, lng + l*HID, lnb + l*HID);
    }
    // after 4 layers: output in g_h (A->B->A->B->A)
    gemm_ab<<<dim3(gb,2), 256>>>();

    edge_k<<<N_EDGES/128, 256, EH_SMEM_BYTES>>>(src, dst, ea, b1, b2, W3, b3, (float*)d_out);
}